// round 4
// baseline (speedup 1.0000x reference)
#include <cuda_runtime.h>

// LocalExpansion: out[b,h,n,k,d] = in[b,h, shifted(n,k), d] with zero pad.
// B=2, H_heads=8, HEIGHT=WIDTH=48, N=2304, K=7x7=49, D=64.
// Pure gather + write: output 231 MB fp32, input 4.7 MB (L2-resident).

#define HEIGHT 48
#define WIDTH  48
#define NPIX   (HEIGHT * WIDTH)   // 2304
#define KH 7
#define KW 7
#define KK (KH * KW)              // 49
#define D  64
#define D4 (D / 4)                // 16 float4 per row
#define ROW4 (KK * D4)            // 784 float4 per output pixel

__global__ void local_expansion_kernel(const float4* __restrict__ in,
                                       float4* __restrict__ out) {
    // blockIdx.x = bh * NPIX + n
    const int n  = blockIdx.x % NPIX;
    const int bh = blockIdx.x / NPIX;

    const int py = n / WIDTH;
    const int px = n % WIDTH;

    const float4* __restrict__ in_bh  = in  + (size_t)bh * NPIX * D4;
    float4* __restrict__       out_px = out + ((size_t)bh * NPIX + n) * ROW4;

    const float4 zero = make_float4(0.f, 0.f, 0.f, 0.f);

    // 784 float4 per pixel; 256 threads -> 3-4 iterations each.
    for (int t = threadIdx.x; t < ROW4; t += blockDim.x) {
        const int d4 = t & (D4 - 1);     // t % 16
        const int k  = t >> 4;           // t / 16
        const int i  = k / KW;
        const int j  = k - i * KW;
        const int y  = py + i - (KH - 1) / 2;
        const int x  = px + j - (KW - 1) / 2;

        float4 v = zero;
        if ((unsigned)y < HEIGHT && (unsigned)x < WIDTH) {
            v = in_bh[(y * WIDTH + x) * D4 + d4];
        }
        out_px[t] = v;
    }
}

extern "C" void kernel_launch(void* const* d_in, const int* in_sizes, int n_in,
                              void* d_out, int out_size) {
    const float4* in = (const float4*)d_in[0];
    float4* out = (float4*)d_out;

    // grid = (B*N_HEADS) * NPIX = 16 * 2304 = 36864 blocks
    dim3 grid(16 * NPIX);
    dim3 block(256);
    local_expansion_kernel<<<grid, block>>>(in, out);
}

// round 5
// speedup vs baseline: 1.2340x; 1.2340x over previous
#include <cuda_runtime.h>

// LocalExpansion: out[b,h,n,k,d] = in[b,h, shifted(n,k), d] with zero pad.
// B=2, H_heads=8, HEIGHT=WIDTH=48, N=2304, K=7x7=49, D=64.
// Output 231 MB fp32 (stores, streaming), input 4.7 MB (must stay L2-resident).
//
// Key change vs R4: __stcs (evict-first) streaming stores keep the 231 MB
// write stream from evicting the 4.7 MB input out of L2, which was costing
// ~175 MB of avoidable DRAM read traffic.

#define HEIGHT 48
#define WIDTH  48
#define NPIX   (HEIGHT * WIDTH)   // 2304
#define KH 7
#define KW 7
#define KK (KH * KW)              // 49
#define D  64
#define D4 (D / 4)                // 16 float4 per row
#define ROW4 (KK * D4)            // 784 float4 per output pixel

__global__ void local_expansion_kernel(const float4* __restrict__ in,
                                       float4* __restrict__ out) {
    const int n  = blockIdx.x;        // pixel
    const int bh = blockIdx.y;        // batch*head

    const int py = n / WIDTH;
    const int px = n % WIDTH;

    const int d4 = threadIdx.x & (D4 - 1);   // 0..15, fixed per thread
    const int ks = threadIdx.x >> 4;         // 0..15, k stride base

    const float4* __restrict__ in_bh =
        in + (size_t)bh * NPIX * D4 + d4;
    float4* __restrict__ out_px =
        out + ((size_t)bh * NPIX + n) * ROW4 + d4;

    const float4 zero = make_float4(0.f, 0.f, 0.f, 0.f);

    // k = ks, ks+16, ks+32 cover k in [0,48); k=48 handled by ks==0 lane group.
    float4 v[3];
    int    kk[3];

    #pragma unroll
    for (int u = 0; u < 3; u++) {
        const int k = ks + 16 * u;
        kk[u] = k;
        const int i = k / KW;
        const int j = k - i * KW;
        const int y = py + i - (KH - 1) / 2;
        const int x = px + j - (KW - 1) / 2;
        v[u] = zero;
        if ((unsigned)y < HEIGHT && (unsigned)x < WIDTH) {
            v[u] = __ldg(in_bh + (y * WIDTH + x) * D4);
        }
    }

    #pragma unroll
    for (int u = 0; u < 3; u++) {
        __stcs(out_px + kk[u] * D4, v[u]);
    }

    if (ks == 0) {
        // k = 48 -> i = 6, j = 6
        const int y = py + 3;
        const int x = px + 3;
        float4 v3 = zero;
        if (y < HEIGHT && x < WIDTH) {
            v3 = __ldg(in_bh + (y * WIDTH + x) * D4);
        }
        __stcs(out_px + 48 * D4, v3);
    }
}

extern "C" void kernel_launch(void* const* d_in, const int* in_sizes, int n_in,
                              void* d_out, int out_size) {
    const float4* in = (const float4*)d_in[0];
    float4* out = (float4*)d_out;

    dim3 grid(NPIX, 16);   // (pixel, batch*head)
    dim3 block(256);
    local_expansion_kernel<<<grid, block>>>(in, out);
}